// round 17
// baseline (speedup 1.0000x reference)
#include <cuda_runtime.h>
#include <cuda_fp16.h>
#include <cstdint>

#define N_PTS   10242
#define C_DIM   64
#define K_DIM   9
#define NBR_DIM 7
#define O_DIM   64
#define BT_DIM  16
#define M_TOTAL (BT_DIM * N_PTS)     /* 163872 */
#define CK_DIM  (C_DIM * K_DIM)      /* 576    */

#define BM       128
#define N_CHUNKS 18                  /* K chunks of 32 */
#define N_TILES  ((M_TOTAL + BM - 1) / BM)   /* 1281 */
/* per (tile, wm, s) block: 36 (ch,ks) planes x 4 regs x 32 lanes = 4608 u32 */
#define SUB_U32  4608

// ---------------- scratch ----------------------------------------------------
// A in MMA A-fragment plane layout:
// [tile][wm][s] blocks of SUB_U32; within: ((ch*2+ks)*4 + reg)*32 + lane
// note: (ch*2+ks) == tapk*4 + c16group
__device__ uint32_t g_Afrag[(size_t)N_TILES * 8 * SUB_U32];
__device__ uint4    g_Wfrag[2 * N_CHUNKS * 2 * 2 * 32];
__device__ int      g_any;

// ---------------- PTX helpers ------------------------------------------------
#define MMA_F16(d, a, b0, b1) \
    asm volatile("mma.sync.aligned.m16n8k16.row.col.f32.f16.f16.f32 " \
        "{%0,%1,%2,%3}, {%4,%5,%6,%7}, {%8,%9}, {%0,%1,%2,%3};" \
        : "+f"((d)[0]), "+f"((d)[1]), "+f"((d)[2]), "+f"((d)[3]) \
        : "r"((a)[0]), "r"((a)[1]), "r"((a)[2]), "r"((a)[3]), "r"(b0), "r"(b1))

// packed fp32x2 fma: d = a*b + d
#define FFMA2(d, a, b) \
    asm("fma.rn.f32x2 %0, %1, %2, %0;" : "+l"(d) : "l"(a), "l"(b))

__device__ __forceinline__ uint32_t cvt_h2(unsigned long long p) {
    uint32_t lo, hi, r;
    asm("mov.b64 {%0, %1}, %2;" : "=r"(lo), "=r"(hi) : "l"(p));
    asm("cvt.rn.f16x2.f32 %0, %1, %2;" : "=r"(r)
        : "f"(__uint_as_float(hi)), "f"(__uint_as_float(lo)));
    return r;
}

// ---------------- setup kernels ----------------------------------------------
__global__ void prepack_wfrag_kernel(const float* __restrict__ conv_w) {
    if (blockIdx.x == 0 && threadIdx.x == 0) g_any = 0;
    int u = blockIdx.x * 256 + threadIdx.x;
    const int TOT = 2 * N_CHUNKS * 2 * 2 * 32 * 4;
    if (u >= TOT) return;
    int j    = u & 3;
    int lane = (u >> 2) & 31;
    int g    = (u >> 7) & 1;
    int ks   = (u >> 8) & 1;
    int ch   = (u >> 9) % N_CHUNKS;
    int wn   = u / (N_CHUNKS * 512);

    int o  = wn * 32 + g * 16 + (j >> 1) * 8 + (lane >> 2);
    int kg = ch * 32 + ks * 16 + (j & 1) * 8 + (lane & 3) * 2;

    float w0 = conv_w[(o * 64 + (kg & 63)) * 9 + (kg >> 6)];
    float w1 = conv_w[(o * 64 + ((kg + 1) & 63)) * 9 + ((kg + 1) >> 6)];
    __half h0 = __float2half_rn(w0);
    __half h1 = __float2half_rn(w1);
    uint32_t packed = ((uint32_t)*(uint16_t*)&h1 << 16) | *(uint16_t*)&h0;
    ((uint32_t*)g_Wfrag)[u] = packed;
}

__global__ void detect_idx_kernel(const int* __restrict__ idx32) {
    int any = 0;
    const int pairs = N_PTS * NBR_DIM / 2;
    for (int i = blockIdx.x * 256 + threadIdx.x; i < pairs; i += gridDim.x * 256)
        any |= (idx32[2 * i + 1] != 0);
    any = __syncthreads_or(any);
    if (threadIdx.x == 0 && any) atomicOr(&g_any, 1);
}

// ---------------- phase 1: interpolation -> A fragments ----------------------
// Block = 32 rows (two 16-row subtiles), 256 thr = 8 warps.
// Warp w: subtile sub=w>>2, channel group c16=w&3 (16 channels).
// Thread t (in warp): r=t>>3, lg=t&7 -> row lg+8*(r&1), chans c16*16+8*(r>>1).
// Per tap k, each thread stores ONE uint4; a warp writes one full 512B plane.
__global__ void __launch_bounds__(256)
interp_kernel(const float* __restrict__ x,
              const void*  __restrict__ index_raw,
              const float* __restrict__ itp_mat) {
    __shared__ float4 sTd[32][NBR_DIM][5];     // duplicated-pair T (17920 B)
    __shared__ int    sIdx[32][NBR_DIM];
    const int tid = threadIdx.x;
    const int m0  = blockIdx.x * 32;
    const int is64 = (g_any == 0);

    for (int i = tid; i < 32 * NBR_DIM * 5; i += 256) {
        int p  = i % 5;
        int j  = (i / 5) % NBR_DIM;
        int mi = i / (5 * NBR_DIM);
        int n  = (m0 + mi) % N_PTS;
        const float* tp = itp_mat + n * 63 + j * K_DIM;
        float ta = tp[2 * p];
        float tb = (2 * p + 1 < K_DIM) ? tp[2 * p + 1] : 0.f;
        sTd[mi][j][p] = make_float4(ta, ta, tb, tb);
    }
    if (tid < 32 * NBR_DIM) {
        int mi = tid / NBR_DIM, j = tid - mi * NBR_DIM;
        int n = (m0 + mi) % N_PTS;
        int v;
        if (is64) v = (int)((const long long*)index_raw)[n * NBR_DIM + j];
        else      v = ((const int*)index_raw)[n * NBR_DIM + j];
        sIdx[mi][j] = v;
    }
    __syncthreads();

    const int w    = tid >> 5;
    const int t    = tid & 31;
    const int sub  = w >> 2;
    const int c16  = w & 3;
    const int r    = t >> 3;
    const int lg   = t & 7;
    const int rloc = sub * 16 + lg + 8 * (r & 1);      // row in block (0..31)
    const int ch8  = c16 * 16 + 8 * (r >> 1);          // first of 8 channels
    const int m    = m0 + rloc;
    const int bt   = m / N_PTS;
    const float* xb = x + (size_t)bt * N_PTS * C_DIM + ch8;

    // acc2[k][q]: q-th packed channel pair (ch8+2q, ch8+2q+1)
    unsigned long long acc2[K_DIM][4];
#pragma unroll
    for (int k = 0; k < K_DIM; k++)
#pragma unroll
        for (int q = 0; q < 4; q++) acc2[k][q] = 0ull;

#pragma unroll
    for (int j = 0; j < NBR_DIM; j++) {
        const float* src = xb + (size_t)sIdx[rloc][j] * C_DIM;
        ulonglong2 v01 = *(const ulonglong2*)(src);      // pairs (0,1),(2,3)
        ulonglong2 v23 = *(const ulonglong2*)(src + 4);  // pairs (4,5),(6,7)
#pragma unroll
        for (int p = 0; p < 5; p++) {
            ulonglong2 tq = *(const ulonglong2*)(&sTd[rloc][j][p]);
            FFMA2(acc2[2 * p][0], v01.x, tq.x);
            FFMA2(acc2[2 * p][1], v01.y, tq.x);
            FFMA2(acc2[2 * p][2], v23.x, tq.x);
            FFMA2(acc2[2 * p][3], v23.y, tq.x);
            if (p < 4) {
                FFMA2(acc2[2 * p + 1][0], v01.x, tq.y);
                FFMA2(acc2[2 * p + 1][1], v01.y, tq.y);
                FFMA2(acc2[2 * p + 1][2], v23.x, tq.y);
                FFMA2(acc2[2 * p + 1][3], v23.y, tq.y);
            }
        }
    }

    // ---- fragment stores: one uint4 per tap, warp-dense 512B planes ----
    // subtile block = blockIdx.x*2 + sub; u32 idx = (k*16 + c16*4 + r)*32 + lg*4
    uint32_t* dbase = g_Afrag + (size_t)(blockIdx.x * 2 + sub) * SUB_U32
                    + (c16 * 4 + r) * 32 + lg * 4;
#pragma unroll
    for (int k = 0; k < K_DIM; k++) {
        uint4 u;
        u.x = cvt_h2(acc2[k][0]);
        u.y = cvt_h2(acc2[k][1]);
        u.z = cvt_h2(acc2[k][2]);
        u.w = cvt_h2(acc2[k][3]);
        __stcs((uint4*)(dbase + k * 512), u);
    }
}

// ---------------- phase 2: HMMA GEMM, pure LDG fragments (no smem) -----------
__global__ void __launch_bounds__(256, 2)
gemm_mma_kernel(const float* __restrict__ conv_b, float* __restrict__ out) {
    const int tid = threadIdx.x;
    const int wid = tid >> 5;
    const int lid = tid & 31;
    const int wm  = wid & 3;
    const int wn  = wid >> 2;
    const int m0  = blockIdx.x * BM;

    float acc[2][4][4];
#pragma unroll
    for (int s = 0; s < 2; s++)
#pragma unroll
        for (int n = 0; n < 4; n++)
#pragma unroll
            for (int q = 0; q < 4; q++) acc[s][n][q] = 0.f;

    const uint32_t* pA = g_Afrag
        + (size_t)(blockIdx.x * 8 + wm * 2) * SUB_U32 + lid;
    const uint4* pW = g_Wfrag + (size_t)(wn * N_CHUNKS) * 4 * 32 + lid;

    uint32_t Ac[2][2][4], An[2][2][4];         // [s][ks][reg]
    uint4 wcur[4], wnxt[4];

#pragma unroll
    for (int s = 0; s < 2; s++)
#pragma unroll
        for (int ks = 0; ks < 2; ks++)
#pragma unroll
            for (int rr = 0; rr < 4; rr++)
                Ac[s][ks][rr] = __ldcs(pA + s * SUB_U32 + ks * 128 + rr * 32);
#pragma unroll
    for (int q = 0; q < 4; q++) wcur[q] = __ldg(pW + q * 32);

    for (int ch = 0; ch < N_CHUNKS; ch++) {
        if (ch + 1 < N_CHUNKS) {
            const int co = (ch + 1) * 256;
#pragma unroll
            for (int s = 0; s < 2; s++)
#pragma unroll
                for (int ks = 0; ks < 2; ks++)
#pragma unroll
                    for (int rr = 0; rr < 4; rr++)
                        An[s][ks][rr] = __ldcs(pA + s * SUB_U32 + co + ks * 128 + rr * 32);
#pragma unroll
            for (int q = 0; q < 4; q++)
                wnxt[q] = __ldg(pW + ((ch + 1) * 4 + q) * 32);
        }

#pragma unroll
        for (int ks = 0; ks < 2; ks++)
#pragma unroll
            for (int s = 0; s < 2; s++)
#pragma unroll
                for (int g = 0; g < 2; g++) {
                    const uint4 w = wcur[ks * 2 + g];
                    MMA_F16(acc[s][g * 2 + 0], Ac[s][ks], w.x, w.y);
                    MMA_F16(acc[s][g * 2 + 1], Ac[s][ks], w.z, w.w);
                }

#pragma unroll
        for (int s = 0; s < 2; s++)
#pragma unroll
            for (int ks = 0; ks < 2; ks++)
#pragma unroll
                for (int rr = 0; rr < 4; rr++)
                    Ac[s][ks][rr] = An[s][ks][rr];
#pragma unroll
        for (int q = 0; q < 4; q++) wcur[q] = wnxt[q];
    }

    // ---- epilogue ----
    float bias[4][2];
#pragma unroll
    for (int n = 0; n < 4; n++) {
        int ob = wn * 32 + n * 8 + (lid & 3) * 2;
        bias[n][0] = __ldg(conv_b + ob);
        bias[n][1] = __ldg(conv_b + ob + 1);
    }
#pragma unroll
    for (int s = 0; s < 2; s++)
#pragma unroll
        for (int h = 0; h < 2; h++) {
            int m = m0 + wm * 32 + s * 16 + h * 8 + (lid >> 2);
            if (m < M_TOTAL) {
                float* op = out + (size_t)m * O_DIM + wn * 32 + (lid & 3) * 2;
#pragma unroll
                for (int n = 0; n < 4; n++) {
                    float2 v;
                    v.x = acc[s][n][h * 2 + 0] + bias[n][0];
                    v.y = acc[s][n][h * 2 + 1] + bias[n][1];
                    *(float2*)(op + n * 8) = v;
                }
            }
        }
}

// ---------------------------------------------------------------------------
extern "C" void kernel_launch(void* const* d_in, const int* in_sizes, int n_in,
                              void* d_out, int out_size) {
    const float* x       = (const float*)d_in[0];
    const void*  index   = d_in[1];
    const float* itp_mat = (const float*)d_in[2];
    const float* conv_w  = (const float*)d_in[3];
    const float* conv_b  = (const float*)d_in[4];
    float*       out     = (float*)d_out;

    prepack_wfrag_kernel<<<144, 256>>>(conv_w);
    detect_idx_kernel<<<64, 256>>>((const int*)index);
    interp_kernel<<<M_TOTAL / 32, 256>>>(x, index, itp_mat);
    gemm_mma_kernel<<<N_TILES, 256>>>(conv_b, out);
}